// round 1
// baseline (speedup 1.0000x reference)
#include <cuda_runtime.h>
#include <cuda_bf16.h>
#include <cstdint>

// Problem constants (from reference): T=32768, E=256, K=8, D=8, r=2
#define E_EXPERTS 256
#define D_DEVS    8
#define K_TOPK    8
#define E_PER_DEV (E_EXPERTS / D_DEVS)   // 32

// expert -> slot-in-permuted-order table (invperm[e] = position of expert e
// after stable sort by device). Computed once per launch by setup_kernel.
__device__ int g_invperm[E_EXPERTS];

__global__ void setup_invperm_kernel(const int* __restrict__ mapping /* [E, D] one-hot */) {
    __shared__ int dev[E_EXPERTS];
    int e = threadIdx.x;
    // argmax over D (first max wins, matching jnp.argmax)
    int best = mapping[e * D_DEVS];
    int d = 0;
#pragma unroll
    for (int i = 1; i < D_DEVS; i++) {
        int v = mapping[e * D_DEVS + i];
        if (v > best) { best = v; d = i; }
    }
    dev[e] = d;
    __syncthreads();
    // stable-sort rank: experts on lower devices first; ties broken by index
    int rank = 0;
    for (int ep = 0; ep < E_EXPERTS; ep++) {
        int de = dev[ep];
        rank += (de < d) || (de == d && ep < e);
    }
    g_invperm[e] = rank;
}

// One warp handles one token PAIR (r=2 reduction group).
// Staging: 512 floats (2 tokens x 256 slots) in smem per warp.
__global__ __launch_bounds__(256) void remap_kernel(
    const float* __restrict__ topk,   // [T, E]
    const int*   __restrict__ meta,   // [T, K]
    float*       __restrict__ out,    // [D, T, 32] remapped
    float*       __restrict__ mask,   // [T/2, D] as float 0/1
    int T)
{
    __shared__ float stage[8][2 * E_EXPERTS];   // 8 warps x 2KB = 16KB

    const int lane = threadIdx.x & 31;
    const int warp = threadIdx.x >> 5;
    const int pair = blockIdx.x * 8 + warp;
    if (pair >= (T >> 1)) return;
    const int t0 = pair << 1;

    float* st = stage[warp];
    float4* st4 = reinterpret_cast<float4*>(st);

    // 1) zero staging (512 floats = 128 float4; 4 per lane)
    const float4 z = make_float4(0.f, 0.f, 0.f, 0.f);
#pragma unroll
    for (int i = 0; i < 4; i++) st4[lane + 32 * i] = z;

    // 2) lanes 0..15 gather the 16 selected scores (8 per token; meta rows contiguous)
    int p = 0;
    float v = 0.f;
    unsigned mbits = 0u;
    if (lane < 16) {
        const int tok = lane >> 3;                      // 0 or 1
        const int e   = meta[t0 * K_TOPK + lane];       // covers both tokens
        p = g_invperm[e];                               // slot in permuted expert order
        v = topk[(size_t)(t0 + tok) * E_EXPERTS + e];   // gathered score
        mbits = 1u << (p >> 5);                         // device bit
    }
    __syncwarp();
    if (lane < 16) {
        const int tok = lane >> 3;
        st[tok * E_EXPERTS + p] = v;                    // scatter into staging
    }
    __syncwarp();

    // 3) pair dispatch mask = OR over all 16 selections (both tokens)
#pragma unroll
    for (int off = 16; off; off >>= 1)
        mbits |= __shfl_xor_sync(0xffffffffu, mbits, off);

    // 4) stream 2KB staging -> global, fully coalesced STG.128
    //    float4 index f in [0,128): tok = f>>6, d = (f&63)>>3, j4 = f&7
#pragma unroll
    for (int i = 0; i < 4; i++) {
        const int f   = lane + 32 * i;
        const int tok = f >> 6;
        const int fd  = f & 63;
        const int d   = fd >> 3;
        const int j4  = fd & 7;
        float4* dst = reinterpret_cast<float4*>(
            out + (size_t)d * T * E_PER_DEV + (size_t)(t0 + tok) * E_PER_DEV + j4 * 4);
        *dst = st4[f];
    }

    // 5) mask write (lanes 0..7)
    if (lane < D_DEVS)
        mask[(size_t)pair * D_DEVS + lane] = ((mbits >> lane) & 1u) ? 1.0f : 0.0f;
}

extern "C" void kernel_launch(void* const* d_in, const int* in_sizes, int n_in,
                              void* d_out, int out_size) {
    const float* topk    = (const float*)d_in[0];   // [1,1,T,E]
    const int*   mapping = (const int*)  d_in[1];   // [1,1,E,D]
    const int*   meta    = (const int*)  d_in[2];   // [1,1,T,K]

    const int T = in_sizes[0] / E_EXPERTS;          // 32768

    float* out  = (float*)d_out;                            // [D, T, 32]
    float* mask = out + (size_t)D_DEVS * T * E_PER_DEV;     // [T/2, D]

    setup_invperm_kernel<<<1, E_EXPERTS>>>(mapping);

    const int pairs = T >> 1;                        // 16384
    const int blocks = (pairs + 7) / 8;              // 8 warps (pairs) per block
    remap_kernel<<<blocks, 256>>>(topk, meta, out, mask, T);
}

// round 2
// speedup vs baseline: 1.1805x; 1.1805x over previous
#include <cuda_runtime.h>
#include <cuda_bf16.h>
#include <cstdint>

// Problem constants: T=32768, E=256, K=8, D=8, r=2
#define E_EXPERTS 256
#define D_DEVS    8
#define K_TOPK    8
#define E_PER_DEV (E_EXPERTS / D_DEVS)   // 32

__device__ int g_invperm[E_EXPERTS];

// Fast rank computation: ballot within warps + cross-warp prefix.
__global__ void setup_invperm_kernel(const int* __restrict__ mapping /* [E, D] */) {
    __shared__ int wcnt[8][8];   // [warp][device] counts
    const int e    = threadIdx.x;        // 256 threads
    const int lane = e & 31;
    const int w    = e >> 5;

    // argmax over D (first max wins, matching jnp.argmax)
    int best = mapping[e * D_DEVS];
    int d = 0;
#pragma unroll
    for (int i = 1; i < D_DEVS; i++) {
        int v = mapping[e * D_DEVS + i];
        if (v > best) { best = v; d = i; }
    }

    const unsigned lt = (1u << lane) - 1u;
    int within = 0;          // rank among same-device experts in my warp, before me
    int mycnt  = 0;          // (lane<8) count of experts on device `lane` in my warp
#pragma unroll
    for (int d2 = 0; d2 < D_DEVS; d2++) {
        unsigned b = __ballot_sync(0xffffffffu, d == d2);
        if (d2 == d)    within = __popc(b & lt);
        if (lane == d2) mycnt  = __popc(b);
    }
    if (lane < D_DEVS) wcnt[w][lane] = mycnt;
    __syncthreads();

    // offset = (#experts on lower devices anywhere) + (#same-device in earlier warps)
    int off = 0;
#pragma unroll
    for (int w2 = 0; w2 < 8; w2++)
#pragma unroll
        for (int d2 = 0; d2 < D_DEVS; d2++) {
            int c = wcnt[w2][d2];
            off += ((d2 < d) || (d2 == d && w2 < w)) ? c : 0;
        }
    g_invperm[e] = off + within;
}

// One warp handles 4 consecutive tokens = 2 reduction pairs.
// lanes 0..31 <-> 32 selections (4 tokens x K=8); single coalesced meta LDG,
// single full-warp gather LDG.
__global__ __launch_bounds__(256) void remap_kernel(
    const float* __restrict__ topk,   // [T, E]
    const int*   __restrict__ meta,   // [T, K]
    float*       __restrict__ out,    // [D, T, 32]
    float*       __restrict__ mask,   // [T/2, D] as float 0/1
    int T)
{
    __shared__ float stage[8][4 * E_EXPERTS];   // 8 warps x 4KB = 32KB

    const int lane = threadIdx.x & 31;
    const int warp = threadIdx.x >> 5;
    const int quad = blockIdx.x * 8 + warp;     // group of 4 tokens
    const int t0   = quad << 2;

    // ---- loads first (deep MLP, overlap with smem zeroing) ----
    const int e    = meta[t0 * K_TOPK + lane];          // 32 contiguous ints
    const int tokl = lane >> 3;                         // 0..3 local token
    const float v  = topk[(t0 + tokl) * E_EXPERTS + e]; // full-warp gather
    const int p    = g_invperm[e];                      // small hot table

    // ---- zero staging: 1024 floats = 256 float4, 8 per lane ----
    float* st = stage[warp];
    float4* st4 = reinterpret_cast<float4*>(st);
    const float4 z = make_float4(0.f, 0.f, 0.f, 0.f);
#pragma unroll
    for (int i = 0; i < 8; i++) st4[lane + 32 * i] = z;
    __syncwarp();

    // ---- scatter selections ----
    st[tokl * E_EXPERTS + p] = v;

    // ---- pair masks: OR within each 16-lane half (one pair each) ----
    unsigned mbits = 1u << (p >> 5);
#pragma unroll
    for (int off = 8; off; off >>= 1)
        mbits |= __shfl_xor_sync(0xffffffffu, mbits, off);
    __syncwarp();

    // ---- stream 4KB staging -> global, coalesced STG.128 ----
    // float4 index f in [0,256): tokl = f>>6, d = (f>>3)&7, j4 = f&7
#pragma unroll
    for (int i = 0; i < 8; i++) {
        const int f  = lane + 32 * i;
        const int tl = f >> 6;
        const int fd = f & 63;
        const int d  = fd >> 3;
        const int j4 = fd & 7;
        float4* dst = reinterpret_cast<float4*>(
            out + d * (T * E_PER_DEV) + (t0 + tl) * E_PER_DEV + j4 * 4);
        *dst = st4[f];
    }

    // ---- mask writes: pair0 by lanes 0..7, pair1 by lanes 16..23 ----
    const int pair0 = quad << 1;
    if (lane < D_DEVS)
        mask[pair0 * D_DEVS + lane] = ((mbits >> lane) & 1u) ? 1.0f : 0.0f;
    else if (lane >= 16 && lane < 16 + D_DEVS)
        mask[(pair0 + 1) * D_DEVS + (lane & 7)] = ((mbits >> (lane & 7)) & 1u) ? 1.0f : 0.0f;
}

extern "C" void kernel_launch(void* const* d_in, const int* in_sizes, int n_in,
                              void* d_out, int out_size) {
    const float* topk    = (const float*)d_in[0];   // [1,1,T,E]
    const int*   mapping = (const int*)  d_in[1];   // [1,1,E,D]
    const int*   meta    = (const int*)  d_in[2];   // [1,1,T,K]

    const int T = in_sizes[0] / E_EXPERTS;          // 32768

    float* out  = (float*)d_out;                            // [D, T, 32]
    float* mask = out + (size_t)D_DEVS * T * E_PER_DEV;     // [T/2, D]

    setup_invperm_kernel<<<1, E_EXPERTS>>>(mapping);

    const int quads  = T >> 2;                       // 8192
    const int blocks = quads / 8;                    // 1024
    remap_kernel<<<blocks, 256>>>(topk, meta, out, mask, T);
}